// round 5
// baseline (speedup 1.0000x reference)
#include <cuda_runtime.h>
#include <cstdint>
#include <cstddef>

#define S_LEN 4096
#define B_SZ  8
#define D_SZ  1024
#define M_TOT (B_SZ * S_LEN)

__device__ float g_gate[(size_t)M_TOT * D_SZ];
__device__ float g_proj[(size_t)M_TOT * D_SZ];
__device__ float g_state[2][B_SZ * D_SZ];
__device__ unsigned g_flag[2][64];

typedef unsigned long long u64;

__device__ __forceinline__ u64 ffma2(u64 a, u64 b, u64 c) {
    u64 d;
    asm("fma.rn.f32x2 %0, %1, %2, %3;" : "=l"(d) : "l"(a), "l"(b), "l"(c));
    return d;
}
__device__ __forceinline__ u64 packdup(float x) {
    u64 r;
    asm("mov.b64 %0, {%1, %1};" : "=l"(r) : "f"(x));
    return r;
}
__device__ __forceinline__ float2 u2f(u64 v) {
    float2 f;
    asm("mov.b64 {%0, %1}, %2;" : "=f"(f.x), "=f"(f.y) : "l"(v));
    return f;
}
__device__ __forceinline__ void st_release(unsigned* p, unsigned v) {
    asm volatile("st.release.gpu.global.u32 [%0], %1;" :: "l"(p), "r"(v) : "memory");
}
__device__ __forceinline__ unsigned ld_acquire(const unsigned* p) {
    unsigned v;
    asm volatile("ld.acquire.gpu.global.u32 %0, [%1];" : "=r"(v) : "l"(p) : "memory");
    return v;
}

// ---------------------------------------------------------------------------
// Phase 1: z = X@Win^T + bin; gate=sigmoid(z[:,:D]); proj=z[:,D:]
// 128x128x8 tile, 256 thr, 8x8 microtile via packed f32x2 (validated R3/R4).
// CTA(0,0) also zeroes recurrence state + flags.
// ---------------------------------------------------------------------------
__global__ __launch_bounds__(256, 2) void phase1_gemm(
    const float* __restrict__ X, const float* __restrict__ Win,
    const float* __restrict__ bin)
{
    __shared__ float As[8][128];
    __shared__ float Bs[8][128];

    const int tid = threadIdx.x;
    const int tx = tid & 15, ty = tid >> 4;
    const int m0 = blockIdx.y * 128, n0 = blockIdx.x * 128;

    if (blockIdx.x == 0 && blockIdx.y == 0) {
        if (tid < 128) ((unsigned*)g_flag)[tid] = 0u;
        for (int i = tid; i < B_SZ * D_SZ; i += 256) g_state[0][i] = 0.0f;
    }

    const int lm = tid >> 1;
    const int lk = (tid & 1) * 4;

    u64 acc[8][4];
    #pragma unroll
    for (int i = 0; i < 8; ++i)
        #pragma unroll
        for (int p = 0; p < 4; ++p) acc[i][p] = 0ull;

    const float* Aptr = X   + (size_t)(m0 + lm) * D_SZ + lk;
    const float* Bptr = Win + (size_t)(n0 + lm) * D_SZ + lk;

    for (int k0 = 0; k0 < D_SZ; k0 += 8) {
        float4 a = *(const float4*)(Aptr + k0);
        float4 b = *(const float4*)(Bptr + k0);
        As[lk + 0][lm] = a.x; As[lk + 1][lm] = a.y;
        As[lk + 2][lm] = a.z; As[lk + 3][lm] = a.w;
        Bs[lk + 0][lm] = b.x; Bs[lk + 1][lm] = b.y;
        Bs[lk + 2][lm] = b.z; Bs[lk + 3][lm] = b.w;
        __syncthreads();

        #pragma unroll
        for (int k = 0; k < 8; ++k) {
            float4 a0 = *(const float4*)&As[k][ty * 8];
            float4 a1 = *(const float4*)&As[k][ty * 8 + 4];
            u64 Ad[8] = {packdup(a0.x), packdup(a0.y), packdup(a0.z), packdup(a0.w),
                         packdup(a1.x), packdup(a1.y), packdup(a1.z), packdup(a1.w)};
            ulonglong2 b01 = *(const ulonglong2*)&Bs[k][tx * 8];
            ulonglong2 b23 = *(const ulonglong2*)&Bs[k][tx * 8 + 4];
            u64 Bp[4] = {b01.x, b01.y, b23.x, b23.y};
            #pragma unroll
            for (int i = 0; i < 8; ++i)
                #pragma unroll
                for (int p = 0; p < 4; ++p)
                    acc[i][p] = ffma2(Ad[i], Bp[p], acc[i][p]);
        }
        __syncthreads();
    }

    const bool is_gate = (n0 < D_SZ);
    #pragma unroll
    for (int i = 0; i < 8; ++i) {
        const int m = m0 + ty * 8 + i;
        #pragma unroll
        for (int p = 0; p < 4; ++p) {
            float2 f = u2f(acc[i][p]);
            const int n = n0 + tx * 8 + 2 * p;
            float v0 = f.x + bin[n];
            float v1 = f.y + bin[n + 1];
            if (is_gate) {
                g_gate[(size_t)m * D_SZ + n]     = 1.0f / (1.0f + __expf(-v0));
                g_gate[(size_t)m * D_SZ + n + 1] = 1.0f / (1.0f + __expf(-v1));
            } else {
                g_proj[(size_t)m * D_SZ + n - D_SZ]     = v0;
                g_proj[(size_t)m * D_SZ + n - D_SZ + 1] = v1;
            }
        }
    }
}

// ---------------------------------------------------------------------------
// Phase 2: 4096-step recurrence, batch-split, flag-array sync.
// 128 CTAs x 256 thr. Group grp=blk>>6 owns batches [4grp,4grp+4);
// chunk=blk&63 owns cols [16chunk,+16). Sync: distributed flags —
// arrival = st.release.gpu flag[grp][chunk]=t+1 (after bar.sync 1,64 among
// the 64 epilogue threads); wait = 64 threads ld.acquire-poll 64 flags.
// ---------------------------------------------------------------------------
__global__ __launch_bounds__(256, 1) void phase2_scan(
    const float* __restrict__ Ws, const float* __restrict__ bs,
    float* __restrict__ out)
{
    __shared__ float4 st4[1024];     // 16 KB: 4 batches x 1024 cols, swizzled
    __shared__ float  pr[4096];      // 16 KB: partials [64 out][64 src], swizzled

    const int tid   = threadIdx.x;
    const int lane  = tid & 31;
    const int w     = tid >> 5;
    const int cg    = w & 3;
    const int kh    = w >> 2;
    const int blk   = blockIdx.x;
    const int grp   = blk >> 6;
    const int chunk = blk & 63;
    const int d0    = 512 * kh + 16 * lane;

    u64 Wn[4][8];
    #pragma unroll
    for (int c = 0; c < 4; ++c) {
        const ulonglong2* wp =
            (const ulonglong2*)&Ws[(size_t)(chunk * 16 + 4 * cg + c) * D_SZ + d0];
        #pragma unroll
        for (int q = 0; q < 4; ++q) {
            ulonglong2 v = wp[q];
            Wn[c][2 * q] = v.x; Wn[c][2 * q + 1] = v.y;
        }
    }

    const int cidx = tid >> 2;
    const int bl   = tid & 3;
    const int ecol = chunk * 16 + cidx;
    const int eb   = 4 * grp + bl;
    const float bsv = (tid < 64) ? bs[ecol] : 0.0f;
    const int sf   = bl * D_SZ + ecol;
    const int sfp  = (((sf >> 2) ^ (((sf >> 2) >> 3) & 7)) << 2) | (sf & 3);

    const int base4 = 128 * kh + 4 * lane;
    const int src   = kh * 32 + lane;
    unsigned* flags = &g_flag[grp][0];

    for (int t = 0; t < S_LEN; ++t) {
        // prefetch gate/proj (independent of state)
        float gv = 0.0f, pv = 0.0f;
        if (tid < 64) {
            size_t gi = ((size_t)eb * S_LEN + t) * D_SZ + ecol;
            gv = __ldcg(&g_gate[gi]);
            pv = __ldcg(&g_proj[gi]);
        }

        // wait: 64 parallel acquire-polls, one flag per thread
        if (tid < 64) {
            while (ld_acquire(&flags[tid]) < (unsigned)t) __nanosleep(20);
        }
        __syncthreads();

        // stage this group's 4-batch state slice (16 KB), swizzled
        const float4* cur = (const float4*)&g_state[t & 1][grp * 4 * D_SZ];
        #pragma unroll
        for (int ii = 0; ii < 4; ++ii) {
            int i = tid + 256 * ii;
            st4[i ^ ((i >> 3) & 7)] = __ldcg(&cur[i]);
        }
        __syncthreads();

        // partial dots: acc[bl][c] packed pairs over lane's 16 d
        u64 ac[4][4];
        #pragma unroll
        for (int b = 0; b < 4; ++b)
            #pragma unroll
            for (int c = 0; c < 4; ++c) ac[b][c] = 0ull;

        #pragma unroll
        for (int b = 0; b < 4; ++b) {
            #pragma unroll
            for (int q = 0; q < 4; ++q) {
                int a = b * 256 + base4 + q;
                ulonglong2 sv = *(const ulonglong2*)&st4[a ^ ((a >> 3) & 7)];
                #pragma unroll
                for (int c = 0; c < 4; ++c) {
                    ac[b][c] = ffma2(Wn[c][2 * q],     sv.x, ac[b][c]);
                    ac[b][c] = ffma2(Wn[c][2 * q + 1], sv.y, ac[b][c]);
                }
            }
        }

        #pragma unroll
        for (int b = 0; b < 4; ++b) {
            #pragma unroll
            for (int c = 0; c < 4; ++c) {
                float2 f = u2f(ac[b][c]);
                int o = ((4 * cg + c) << 2) | b;
                int a = o * 16 + (src >> 2);
                pr[((a ^ ((a >> 4) & 7)) << 2) | (src & 3)] = f.x + f.y;
            }
        }
        __syncthreads();

        // reduce + gated epilogue + early release (threads 0..63 only)
        if (tid < 64) {
            float sum = 0.0f;
            #pragma unroll
            for (int q = 0; q < 16; ++q) {
                int a = tid * 16 + q;
                float4 v = ((const float4*)pr)[a ^ ((a >> 4) & 7)];
                sum += (v.x + v.y) + (v.z + v.w);
            }
            float mix  = sum + bsv + pv;
            float sold = ((const float*)st4)[sfp];
            float nxt  = gv * mix + (1.0f - gv) * sold;
            out[((size_t)eb * S_LEN + t) * D_SZ + ecol] = nxt;
            __stcg(&g_state[(t + 1) & 1][eb * D_SZ + ecol], nxt);
            asm volatile("bar.sync 1, 64;" ::: "memory");
            if (tid == 0) st_release(&flags[chunk], (unsigned)(t + 1));
        }
        // warps 2..7 run ahead to the next poll/syncthreads; safe because
        // staging (t+1) happens only after all threads pass that syncthreads,
        // and threads 0..63 arrive there only after reading st4/pr here.
    }
}

// ---------------------------------------------------------------------------
extern "C" void kernel_launch(void* const* d_in, const int* in_sizes, int n_in,
                              void* d_out, int out_size) {
    const float* x    = (const float*)d_in[0];
    const float* W_in = (const float*)d_in[1];
    const float* b_in = (const float*)d_in[2];
    const float* W_s  = (const float*)d_in[3];
    const float* b_s  = (const float*)d_in[4];
    float* out = (float*)d_out;

    dim3 g1(16, 256);
    phase1_gemm<<<g1, 256>>>(x, W_in, b_in);
    phase2_scan<<<128, 256>>>(W_s, b_s, out);
}

// round 7
// speedup vs baseline: 1.2359x; 1.2359x over previous
#include <cuda_runtime.h>
#include <cuda_bf16.h>
#include <cstdint>
#include <cstddef>

#define S_LEN 4096
#define B_SZ  8
#define D_SZ  1024
#define M_TOT (B_SZ * S_LEN)

__device__ float g_gate[(size_t)M_TOT * D_SZ];
__device__ float g_proj[(size_t)M_TOT * D_SZ];
__device__ float g_state[2][B_SZ * D_SZ];
__device__ unsigned g_cnt[2];

typedef unsigned long long u64;

__device__ __forceinline__ u64 ffma2(u64 a, u64 b, u64 c) {
    u64 d;
    asm("fma.rn.f32x2 %0, %1, %2, %3;" : "=l"(d) : "l"(a), "l"(b), "l"(c));
    return d;
}
__device__ __forceinline__ float2 u2f(u64 v) {
    float2 f;
    asm("mov.b64 {%0, %1}, %2;" : "=f"(f.x), "=f"(f.y) : "l"(v));
    return f;
}
__device__ __forceinline__ void mma16816(float* c, const unsigned* a,
                                         unsigned b0, unsigned b1) {
    asm("mma.sync.aligned.m16n8k16.row.col.f32.bf16.bf16.f32 "
        "{%0,%1,%2,%3}, {%4,%5,%6,%7}, {%8,%9}, {%0,%1,%2,%3};"
        : "+f"(c[0]), "+f"(c[1]), "+f"(c[2]), "+f"(c[3])
        : "r"(a[0]), "r"(a[1]), "r"(a[2]), "r"(a[3]), "r"(b0), "r"(b1));
}
// pack two fp32 into bf16x2 (hi parts) and residual bf16x2 (lo parts)
__device__ __forceinline__ void cvt_hilo(float x, float y,
                                         unsigned& h, unsigned& l) {
    __nv_bfloat16 hx = __float2bfloat16_rn(x);
    __nv_bfloat16 hy = __float2bfloat16_rn(y);
    __nv_bfloat16 lx = __float2bfloat16_rn(x - __bfloat162float(hx));
    __nv_bfloat16 ly = __float2bfloat16_rn(y - __bfloat162float(hy));
    h = (unsigned)__bfloat16_as_ushort(hx) | ((unsigned)__bfloat16_as_ushort(hy) << 16);
    l = (unsigned)__bfloat16_as_ushort(lx) | ((unsigned)__bfloat16_as_ushort(ly) << 16);
}

#define STRIDE 17   // u32 stride per 32-bf16 row (padded: 16 data + 1)

// ---------------------------------------------------------------------------
// Phase 1: z = X@Win^T + bin via mma.sync bf16 hi/lo split (3 terms).
// CTA 128x128, K in 32-blocks. 8 warps: warp_m=w&3 (32 rows), warp_n=w>>2
// (64 cols). fp32 -> bf16 hi/lo conversion fused into smem staging.
// CTA(0,0) also zeroes recurrence state + counters.
// ---------------------------------------------------------------------------
__global__ __launch_bounds__(256, 2) void phase1_hmma(
    const float* __restrict__ X, const float* __restrict__ Win,
    const float* __restrict__ bin)
{
    __shared__ unsigned Ah[128 * STRIDE], Al[128 * STRIDE];
    __shared__ unsigned Bh[128 * STRIDE], Bl[128 * STRIDE];

    const int tid = threadIdx.x;
    const int m0 = blockIdx.y * 128, n0 = blockIdx.x * 128;

    if (blockIdx.x == 0 && blockIdx.y == 0) {
        if (tid == 0) { g_cnt[0] = 0u; g_cnt[1] = 0u; }
        for (int i = tid; i < B_SZ * D_SZ; i += 256) g_state[0][i] = 0.0f;
    }

    const int lane = tid & 31, w = tid >> 5;
    const int m_off = (w & 3) * 32;       // warp row base (within tile)
    const int n_off = (w >> 2) * 64;      // warp col base

    // staging assignment: row = tid/2 (0..127), k half = (tid&1)*16
    const int srow = tid >> 1;
    const int skh  = (tid & 1) * 16;
    const float* Ap = X   + (size_t)(m0 + srow) * D_SZ + skh;
    const float* Bp = Win + (size_t)(n0 + srow) * D_SZ + skh;
    const int sb32 = srow * STRIDE + (skh >> 1);

    float C[2][8][4];
    #pragma unroll
    for (int mt = 0; mt < 2; ++mt)
        #pragma unroll
        for (int nt = 0; nt < 8; ++nt)
            #pragma unroll
            for (int q = 0; q < 4; ++q) C[mt][nt][q] = 0.0f;

    const int fr = lane >> 2;            // fragment row/col base 0..7
    const int fc = lane & 3;             // fragment k quad

    for (int k0 = 0; k0 < D_SZ; k0 += 32) {
        // ---- stage + convert ----
        #pragma unroll
        for (int j = 0; j < 4; ++j) {
            float4 a = *(const float4*)(Ap + k0 + 4 * j);
            unsigned h0, l0, h1, l1;
            cvt_hilo(a.x, a.y, h0, l0);
            cvt_hilo(a.z, a.w, h1, l1);
            Ah[sb32 + 2 * j] = h0; Ah[sb32 + 2 * j + 1] = h1;
            Al[sb32 + 2 * j] = l0; Al[sb32 + 2 * j + 1] = l1;
            float4 b = *(const float4*)(Bp + k0 + 4 * j);
            cvt_hilo(b.x, b.y, h0, l0);
            cvt_hilo(b.z, b.w, h1, l1);
            Bh[sb32 + 2 * j] = h0; Bh[sb32 + 2 * j + 1] = h1;
            Bl[sb32 + 2 * j] = l0; Bl[sb32 + 2 * j + 1] = l1;
        }
        __syncthreads();

        // ---- compute: two k16 steps ----
        #pragma unroll
        for (int ks = 0; ks < 2; ++ks) {
            const int cb = ks * 8 + fc;   // b32 col base in padded row
            unsigned ah[2][4], al[2][4];
            #pragma unroll
            for (int mt = 0; mt < 2; ++mt) {
                int r = m_off + mt * 16 + fr;
                ah[mt][0] = Ah[r * STRIDE + cb];
                ah[mt][1] = Ah[(r + 8) * STRIDE + cb];
                ah[mt][2] = Ah[r * STRIDE + cb + 4];
                ah[mt][3] = Ah[(r + 8) * STRIDE + cb + 4];
                al[mt][0] = Al[r * STRIDE + cb];
                al[mt][1] = Al[(r + 8) * STRIDE + cb];
                al[mt][2] = Al[r * STRIDE + cb + 4];
                al[mt][3] = Al[(r + 8) * STRIDE + cb + 4];
            }
            #pragma unroll
            for (int nt = 0; nt < 8; ++nt) {
                int n = n_off + nt * 8 + fr;
                unsigned bh0 = Bh[n * STRIDE + cb], bh1 = Bh[n * STRIDE + cb + 4];
                unsigned bl0 = Bl[n * STRIDE + cb], bl1 = Bl[n * STRIDE + cb + 4];
                #pragma unroll
                for (int mt = 0; mt < 2; ++mt) {
                    mma16816(C[mt][nt], ah[mt], bh0, bh1);
                    mma16816(C[mt][nt], ah[mt], bl0, bl1);
                    mma16816(C[mt][nt], al[mt], bh0, bh1);
                }
            }
        }
        __syncthreads();
    }

    // ---- epilogue: bias + sigmoid split ----
    const bool is_gate = (n0 < D_SZ);
    float* dst = is_gate ? g_gate : g_proj;
    const int csub = is_gate ? 0 : D_SZ;
    #pragma unroll
    for (int mt = 0; mt < 2; ++mt) {
        const int r = m0 + m_off + mt * 16 + fr;
        #pragma unroll
        for (int nt = 0; nt < 8; ++nt) {
            const int cn = n0 + n_off + nt * 8 + fc * 2;
            float b0 = bin[cn], b1 = bin[cn + 1];
            float v0 = C[mt][nt][0] + b0, v1 = C[mt][nt][1] + b1;
            float v2 = C[mt][nt][2] + b0, v3 = C[mt][nt][3] + b1;
            if (is_gate) {
                v0 = 1.0f / (1.0f + __expf(-v0));
                v1 = 1.0f / (1.0f + __expf(-v1));
                v2 = 1.0f / (1.0f + __expf(-v2));
                v3 = 1.0f / (1.0f + __expf(-v3));
            }
            *(float2*)&dst[(size_t)r * D_SZ + cn - csub]       = make_float2(v0, v1);
            *(float2*)&dst[(size_t)(r + 8) * D_SZ + cn - csub] = make_float2(v2, v3);
        }
    }
}

// ---------------------------------------------------------------------------
// Phase 2: exact R4 scheme (proven). 128 CTAs x 256 thr,
// 2 groups of 64 CTAs, central atomic counter per group.
// ---------------------------------------------------------------------------
__global__ __launch_bounds__(256, 1) void phase2_scan(
    const float* __restrict__ Ws, const float* __restrict__ bs,
    float* __restrict__ out)
{
    __shared__ float4 st4[1024];
    __shared__ float  pr[4096];

    const int tid   = threadIdx.x;
    const int lane  = tid & 31;
    const int w     = tid >> 5;
    const int cg    = w & 3;
    const int kh    = w >> 2;
    const int blk   = blockIdx.x;
    const int grp   = blk >> 6;
    const int chunk = blk & 63;
    const int d0    = 512 * kh + 16 * lane;

    u64 Wn[4][8];
    #pragma unroll
    for (int c = 0; c < 4; ++c) {
        const ulonglong2* wp =
            (const ulonglong2*)&Ws[(size_t)(chunk * 16 + 4 * cg + c) * D_SZ + d0];
        #pragma unroll
        for (int q = 0; q < 4; ++q) {
            ulonglong2 v = wp[q];
            Wn[c][2 * q] = v.x; Wn[c][2 * q + 1] = v.y;
        }
    }

    const int cidx = tid >> 2;
    const int bl   = tid & 3;
    const int ecol = chunk * 16 + cidx;
    const int eb   = 4 * grp + bl;
    const float bsv = (tid < 64) ? bs[ecol] : 0.0f;
    const int sf   = bl * D_SZ + ecol;
    const int sfp  = (((sf >> 2) ^ (((sf >> 2) >> 3) & 7)) << 2) | (sf & 3);

    const int base4 = 128 * kh + 4 * lane;
    const int src   = kh * 32 + lane;
    volatile unsigned* cnt = (volatile unsigned*)&g_cnt[grp];

    for (int t = 0; t < S_LEN; ++t) {
        float gv = 0.0f, pv = 0.0f;
        if (tid < 64) {
            size_t gi = ((size_t)eb * S_LEN + t) * D_SZ + ecol;
            gv = __ldcg(&g_gate[gi]);
            pv = __ldcg(&g_proj[gi]);
        }

        if (tid == 0) {
            unsigned target = (unsigned)(64 * t);
            while (*cnt < target) __nanosleep(20);
            __threadfence();
        }
        __syncthreads();

        const float4* cur = (const float4*)&g_state[t & 1][grp * 4 * D_SZ];
        #pragma unroll
        for (int ii = 0; ii < 4; ++ii) {
            int i = tid + 256 * ii;
            st4[i ^ ((i >> 3) & 7)] = __ldcg(&cur[i]);
        }
        __syncthreads();

        u64 ac[4][4];
        #pragma unroll
        for (int b = 0; b < 4; ++b)
            #pragma unroll
            for (int c = 0; c < 4; ++c) ac[b][c] = 0ull;

        #pragma unroll
        for (int b = 0; b < 4; ++b) {
            #pragma unroll
            for (int q = 0; q < 4; ++q) {
                int a = b * 256 + base4 + q;
                ulonglong2 sv = *(const ulonglong2*)&st4[a ^ ((a >> 3) & 7)];
                #pragma unroll
                for (int c = 0; c < 4; ++c) {
                    ac[b][c] = ffma2(Wn[c][2 * q],     sv.x, ac[b][c]);
                    ac[b][c] = ffma2(Wn[c][2 * q + 1], sv.y, ac[b][c]);
                }
            }
        }

        #pragma unroll
        for (int b = 0; b < 4; ++b) {
            #pragma unroll
            for (int c = 0; c < 4; ++c) {
                float2 f = u2f(ac[b][c]);
                int o = ((4 * cg + c) << 2) | b;
                int a = o * 16 + (src >> 2);
                pr[((a ^ ((a >> 4) & 7)) << 2) | (src & 3)] = f.x + f.y;
            }
        }
        __syncthreads();

        if (tid < 64) {
            float sum = 0.0f;
            #pragma unroll
            for (int q = 0; q < 16; ++q) {
                int a = tid * 16 + q;
                float4 v = ((const float4*)pr)[a ^ ((a >> 4) & 7)];
                sum += (v.x + v.y) + (v.z + v.w);
            }
            float mix  = sum + bsv + pv;
            float sold = ((const float*)st4)[sfp];
            float nxt  = gv * mix + (1.0f - gv) * sold;
            out[((size_t)eb * S_LEN + t) * D_SZ + ecol] = nxt;
            __stcg(&g_state[(t + 1) & 1][eb * D_SZ + ecol], nxt);
        }
        __syncthreads();

        if (tid == 0) {
            __threadfence();
            atomicAdd(&g_cnt[grp], 1u);
        }
    }
}

// ---------------------------------------------------------------------------
extern "C" void kernel_launch(void* const* d_in, const int* in_sizes, int n_in,
                              void* d_out, int out_size) {
    const float* x    = (const float*)d_in[0];
    const float* W_in = (const float*)d_in[1];
    const float* b_in = (const float*)d_in[2];
    const float* W_s  = (const float*)d_in[3];
    const float* b_s  = (const float*)d_in[4];
    float* out = (float*)d_out;

    dim3 g1(16, 256);   // N tiles x M tiles
    phase1_hmma<<<g1, 256>>>(x, W_in, b_in);
    phase2_scan<<<128, 256>>>(W_s, b_s, out);
}